// round 5
// baseline (speedup 1.0000x reference)
#include <cuda_runtime.h>
#include <cstdint>

// Problem constants (shapes fixed by the dataset)
#define NBATCH 2
#define FDIM   128
#define NMAX   50000
#define EMAX   800000

// Scratch (device globals; no allocation allowed)
__device__ float g_deg[NMAX];
__device__ float g_dinv[NMAX];
__device__ int   g_cnt[NMAX];        // in-edge counts (by row)
__device__ int   g_rowstart[NMAX];   // CSR row starts
__device__ int   g_cursor[NMAX];     // fill cursors
__device__ int2  g_csr[EMAX];        // {col, __float_as_int(norm)}
__device__ float g_xlin[(size_t)NBATCH * NMAX * FDIM];   // 51.2 MB
__device__ float g_Wt[FDIM * FDIM];                      // W transposed: [f][o]

// ---------------------------------------------------------------- K0: deg=1 (self loop), cnt=0
__global__ void k_init(int N) {
    int i = blockIdx.x * blockDim.x + threadIdx.x;
    if (i < N) { g_deg[i] = 1.0f; g_cnt[i] = 0; }
}

// ---------------------------------------------------------------- K1: deg[row] += w; cnt[row]++
__global__ void k_deg_cnt(const int* __restrict__ ei, const float* __restrict__ ea, int E) {
    int e = blockIdx.x * blockDim.x + threadIdx.x;
    if (e < E) {
        int r = ei[e];
        atomicAdd(&g_deg[r], ea[e]);
        atomicAdd(&g_cnt[r], 1);
    }
}

// ---------------------------------------------------------------- K2: Wt[f][o] = W[o][f]
__global__ void k_wt(const float* __restrict__ W) {
    int i = blockIdx.x * blockDim.x + threadIdx.x;   // i = f*128 + o
    if (i < FDIM * FDIM) {
        int f = i >> 7, o = i & 127;
        g_Wt[i] = W[o * FDIM + f];
    }
}

// ---------------------------------------------------------------- K3: single-block scan + dinv
// rowstart = exclusive prefix of cnt; cursor = rowstart; dinv = rsqrt(deg)
__global__ void k_scan_dinv(int N) {
    __shared__ int part[1024];
    const int t = threadIdx.x;
    const int chunk = (N + 1023) / 1024;
    const int begin = t * chunk;
    const int end   = min(begin + chunk, N);

    int s = 0;
    for (int i = begin; i < end; i++) {
        s += g_cnt[i];
        float d = g_deg[i];
        g_dinv[i] = (d > 0.0f) ? rsqrtf(d) : 0.0f;
    }
    part[t] = s;
    __syncthreads();
    // Hillis-Steele inclusive scan over 1024 partials
    for (int off = 1; off < 1024; off <<= 1) {
        int v = (t >= off) ? part[t - off] : 0;
        __syncthreads();
        part[t] += v;
        __syncthreads();
    }
    int run = (t == 0) ? 0 : part[t - 1];
    for (int i = begin; i < end; i++) {
        g_rowstart[i] = run;
        g_cursor[i]   = run;
        run += g_cnt[i];
    }
}

// ---------------------------------------------------------------- K4: fill CSR with premultiplied norm
__global__ void k_fill(const int* __restrict__ ei, const float* __restrict__ ea, int E) {
    int e = blockIdx.x * blockDim.x + threadIdx.x;
    if (e < E) {
        int r = ei[e];
        int c = ei[E + e];
        float norm = g_dinv[r] * ea[e] * g_dinv[c];
        int p = atomicAdd(&g_cursor[r], 1);
        g_csr[p] = make_int2(c, __float_as_int(norm));
    }
}

// ---------------------------------------------------------------- K5: GEMM -> x_lin
// x_lin[rr][o] = sum_f x[rr][f] * W[o][f] + bias[o]      (rr = b*N + n)
#define GEMM_ROWS 64
__global__ void k_gemm(const float* __restrict__ x, const float* __restrict__ bias, int BN) {
    extern __shared__ float sm[];
    float* Ws = sm;                      // [128][128] (row = f)
    float* xs = sm + FDIM * FDIM;        // [64][128]
    const int tid = threadIdx.x;
    const int row0 = blockIdx.x * GEMM_ROWS;

    for (int i = tid; i < FDIM * FDIM; i += 256)
        Ws[i] = g_Wt[i];
    for (int i = tid; i < GEMM_ROWS * FDIM; i += 256) {
        int gr = row0 + (i >> 7);
        xs[i] = (gr < BN) ? x[(size_t)gr * FDIM + (i & 127)] : 0.0f;
    }
    __syncthreads();

    const int tx = tid & 31;
    const int ty = tid >> 5;
    float acc[8][4];
    const float4 b4 = *(const float4*)(bias + 4 * tx);
#pragma unroll
    for (int r = 0; r < 8; r++) {
        acc[r][0] = b4.x; acc[r][1] = b4.y; acc[r][2] = b4.z; acc[r][3] = b4.w;
    }

#pragma unroll 4
    for (int f = 0; f < FDIM; f++) {
        float4 wv = *(const float4*)&Ws[f * FDIM + 4 * tx];
#pragma unroll
        for (int r = 0; r < 8; r++) {
            float xv = xs[(ty * 8 + r) * FDIM + f];
            acc[r][0] = fmaf(xv, wv.x, acc[r][0]);
            acc[r][1] = fmaf(xv, wv.y, acc[r][1]);
            acc[r][2] = fmaf(xv, wv.z, acc[r][2]);
            acc[r][3] = fmaf(xv, wv.w, acc[r][3]);
        }
    }

#pragma unroll
    for (int r = 0; r < 8; r++) {
        int rr = row0 + ty * 8 + r;
        if (rr < BN) {
            ((float4*)g_xlin)[(size_t)rr * 32 + tx] =
                make_float4(acc[r][0], acc[r][1], acc[r][2], acc[r][3]);
        }
    }
}

// ---------------------------------------------------------------- K6: gather (warp per node) + self loop + relu
__global__ void k_gather(float* __restrict__ out, int N) {
    int n = (blockIdx.x * blockDim.x + threadIdx.x) >> 5;
    int lane = threadIdx.x & 31;
    if (n >= N) return;

    const int start = g_rowstart[n];
    const int num   = g_cnt[n];
    const float4* __restrict__ xl = (const float4*)g_xlin;
    const int N32 = N * 32;

    float4 a0 = make_float4(0.f, 0.f, 0.f, 0.f);
    float4 a1 = make_float4(0.f, 0.f, 0.f, 0.f);

    for (int i = 0; i < num; i++) {
        int2 ed = g_csr[start + i];            // broadcast load (all lanes same addr)
        int   c = ed.x;
        float w = __int_as_float(ed.y);
        float4 v0 = xl[c * 32 + lane];         // batch 0
        float4 v1 = xl[N32 + c * 32 + lane];   // batch 1
        a0.x = fmaf(w, v0.x, a0.x); a0.y = fmaf(w, v0.y, a0.y);
        a0.z = fmaf(w, v0.z, a0.z); a0.w = fmaf(w, v0.w, a0.w);
        a1.x = fmaf(w, v1.x, a1.x); a1.y = fmaf(w, v1.y, a1.y);
        a1.z = fmaf(w, v1.z, a1.z); a1.w = fmaf(w, v1.w, a1.w);
    }

    float di = g_dinv[n];
    float sn = di * di;
    float4 s0 = xl[n * 32 + lane];
    float4 s1 = xl[N32 + n * 32 + lane];
    float4 o0 = make_float4(fmaxf(fmaf(sn, s0.x, a0.x), 0.f),
                            fmaxf(fmaf(sn, s0.y, a0.y), 0.f),
                            fmaxf(fmaf(sn, s0.z, a0.z), 0.f),
                            fmaxf(fmaf(sn, s0.w, a0.w), 0.f));
    float4 o1 = make_float4(fmaxf(fmaf(sn, s1.x, a1.x), 0.f),
                            fmaxf(fmaf(sn, s1.y, a1.y), 0.f),
                            fmaxf(fmaf(sn, s1.z, a1.z), 0.f),
                            fmaxf(fmaf(sn, s1.w, a1.w), 0.f));
    ((float4*)out)[n * 32 + lane]       = o0;
    ((float4*)out)[N32 + n * 32 + lane] = o1;
}

// ---------------------------------------------------------------- launch
extern "C" void kernel_launch(void* const* d_in, const int* in_sizes, int n_in,
                              void* d_out, int out_size) {
    const float* x    = (const float*)d_in[0];
    const int*   ei   = (const int*)d_in[1];     // int32 (JAX x64 disabled)
    const float* ea   = (const float*)d_in[2];
    const float* W    = (const float*)d_in[3];
    const float* bias = (const float*)d_in[4];
    float*       out  = (float*)d_out;

    const int E  = in_sizes[2];                    // 800000
    const int N  = in_sizes[0] / (NBATCH * FDIM);  // 50000
    const int BN = NBATCH * N;

    k_init<<<(N + 255) / 256, 256>>>(N);
    k_deg_cnt<<<(E + 255) / 256, 256>>>(ei, ea, E);
    k_wt<<<(FDIM * FDIM + 255) / 256, 256>>>(W);
    k_scan_dinv<<<1, 1024>>>(N);
    k_fill<<<(E + 255) / 256, 256>>>(ei, ea, E);

    int smem = (FDIM * FDIM + GEMM_ROWS * FDIM) * (int)sizeof(float);  // 96 KB
    cudaFuncSetAttribute(k_gemm, cudaFuncAttributeMaxDynamicSharedMemorySize, smem);
    k_gemm<<<(BN + GEMM_ROWS - 1) / GEMM_ROWS, 256, smem>>>(x, bias, BN);

    k_gather<<<(N * 32 + 255) / 256, 256>>>(out, N);
}

// round 8
// speedup vs baseline: 1.5839x; 1.5839x over previous
#include <cuda_runtime.h>
#include <cstdint>

// Problem constants (shapes fixed by the dataset)
#define NBATCH 2
#define FDIM   128
#define NMAX   50000
#define EMAX   800000

// Scratch (device globals; no allocation allowed)
__device__ float g_deg[NMAX];
__device__ float g_dinv[NMAX];
__device__ int   g_cnt[NMAX];        // in-edge counts (by row)
__device__ int   g_rowstart[NMAX];   // CSR row starts (bump-allocated, NOT node-ordered)
__device__ int   g_cursor[NMAX];     // fill cursors
__device__ int   g_total;            // bump allocator
__device__ int2  g_csr[EMAX];        // {col, __float_as_int(norm)}
__device__ float g_xlin[(size_t)NBATCH * NMAX * FDIM];   // 51.2 MB
__device__ float g_Wt[FDIM * FDIM];                      // W transposed: [f][o]

// ---------------------------------------------------------------- K0: deg=1 (self loop), cnt=0
__global__ void k_init(int N) {
    int i = blockIdx.x * blockDim.x + threadIdx.x;
    if (i < N) { g_deg[i] = 1.0f; g_cnt[i] = 0; }
    if (i == 0) g_total = 0;
}

// ---------------------------------------------------------------- K1: deg[row] += w; cnt[row]++
__global__ void k_deg_cnt(const int* __restrict__ ei, const float* __restrict__ ea, int E) {
    int e = blockIdx.x * blockDim.x + threadIdx.x;
    if (e < E) {
        int r = ei[e];
        atomicAdd(&g_deg[r], ea[e]);
        atomicAdd(&g_cnt[r], 1);
    }
}

// ---------------------------------------------------------------- K2: Wt[f][o] = W[o][f]
__global__ void k_wt(const float* __restrict__ W) {
    int i = blockIdx.x * blockDim.x + threadIdx.x;   // i = f*128 + o
    if (i < FDIM * FDIM) {
        int f = i >> 7, o = i & 127;
        g_Wt[i] = W[o * FDIM + f];
    }
}

// ---------------------------------------------------------------- K3: segment alloc (warp-aggregated bump) + dinv
// rowstart[n] = bump-allocated start for cnt[n] edges; cursor = rowstart; dinv = rsqrt(deg)
__global__ void k_alloc_dinv(int N) {
    int i = blockIdx.x * blockDim.x + threadIdx.x;
    int lane = threadIdx.x & 31;
    int v = (i < N) ? g_cnt[i] : 0;

    // warp inclusive scan of counts
    int incl = v;
#pragma unroll
    for (int off = 1; off < 32; off <<= 1) {
        int t = __shfl_up_sync(0xffffffffu, incl, off);
        if (lane >= off) incl += t;
    }
    int excl = incl - v;
    int warp_sum = __shfl_sync(0xffffffffu, incl, 31);

    int base = 0;
    if (lane == 0 && warp_sum > 0) base = atomicAdd(&g_total, warp_sum);
    base = __shfl_sync(0xffffffffu, base, 0);

    if (i < N) {
        int s = base + excl;
        g_rowstart[i] = s;
        g_cursor[i]   = s;
        float d = g_deg[i];
        g_dinv[i] = (d > 0.0f) ? rsqrtf(d) : 0.0f;
    }
}

// ---------------------------------------------------------------- K4: fill CSR with premultiplied norm
__global__ void k_fill(const int* __restrict__ ei, const float* __restrict__ ea, int E) {
    int e = blockIdx.x * blockDim.x + threadIdx.x;
    if (e < E) {
        int r = ei[e];
        int c = ei[E + e];
        float norm = g_dinv[r] * ea[e] * g_dinv[c];
        int p = atomicAdd(&g_cursor[r], 1);
        g_csr[p] = make_int2(c, __float_as_int(norm));
    }
}

// ---------------------------------------------------------------- K5: GEMM -> x_lin
// x_lin[rr][o] = sum_f x[rr][f] * W[o][f] + bias[o]      (rr = b*N + n)
#define GEMM_ROWS 64
__global__ void k_gemm(const float* __restrict__ x, const float* __restrict__ bias, int BN) {
    extern __shared__ float sm[];
    float* Ws = sm;                      // [128][128] (row = f)
    float* xs = sm + FDIM * FDIM;        // [64][128]
    const int tid = threadIdx.x;
    const int row0 = blockIdx.x * GEMM_ROWS;

    for (int i = tid; i < FDIM * FDIM; i += 256)
        Ws[i] = g_Wt[i];
    for (int i = tid; i < GEMM_ROWS * FDIM; i += 256) {
        int gr = row0 + (i >> 7);
        xs[i] = (gr < BN) ? x[(size_t)gr * FDIM + (i & 127)] : 0.0f;
    }
    __syncthreads();

    const int tx = tid & 31;
    const int ty = tid >> 5;
    float acc[8][4];
    const float4 b4 = *(const float4*)(bias + 4 * tx);
#pragma unroll
    for (int r = 0; r < 8; r++) {
        acc[r][0] = b4.x; acc[r][1] = b4.y; acc[r][2] = b4.z; acc[r][3] = b4.w;
    }

#pragma unroll 4
    for (int f = 0; f < FDIM; f++) {
        float4 wv = *(const float4*)&Ws[f * FDIM + 4 * tx];
#pragma unroll
        for (int r = 0; r < 8; r++) {
            float xv = xs[(ty * 8 + r) * FDIM + f];
            acc[r][0] = fmaf(xv, wv.x, acc[r][0]);
            acc[r][1] = fmaf(xv, wv.y, acc[r][1]);
            acc[r][2] = fmaf(xv, wv.z, acc[r][2]);
            acc[r][3] = fmaf(xv, wv.w, acc[r][3]);
        }
    }

#pragma unroll
    for (int r = 0; r < 8; r++) {
        int rr = row0 + ty * 8 + r;
        if (rr < BN) {
            ((float4*)g_xlin)[(size_t)rr * 32 + tx] =
                make_float4(acc[r][0], acc[r][1], acc[r][2], acc[r][3]);
        }
    }
}

// ---------------------------------------------------------------- K6: gather (warp per node) + self loop + relu
__global__ void k_gather(float* __restrict__ out, int N) {
    int n = (blockIdx.x * blockDim.x + threadIdx.x) >> 5;
    int lane = threadIdx.x & 31;
    if (n >= N) return;

    const int start = g_rowstart[n];
    const int num   = g_cnt[n];
    const float4* __restrict__ xl = (const float4*)g_xlin;
    const int N32 = N * 32;

    float4 a0 = make_float4(0.f, 0.f, 0.f, 0.f);
    float4 a1 = make_float4(0.f, 0.f, 0.f, 0.f);

    for (int i = 0; i < num; i++) {
        int2 ed = g_csr[start + i];            // broadcast load (all lanes same addr)
        int   c = ed.x;
        float w = __int_as_float(ed.y);
        float4 v0 = xl[c * 32 + lane];         // batch 0
        float4 v1 = xl[N32 + c * 32 + lane];   // batch 1
        a0.x = fmaf(w, v0.x, a0.x); a0.y = fmaf(w, v0.y, a0.y);
        a0.z = fmaf(w, v0.z, a0.z); a0.w = fmaf(w, v0.w, a0.w);
        a1.x = fmaf(w, v1.x, a1.x); a1.y = fmaf(w, v1.y, a1.y);
        a1.z = fmaf(w, v1.z, a1.z); a1.w = fmaf(w, v1.w, a1.w);
    }

    float di = g_dinv[n];
    float sn = di * di;
    float4 s0 = xl[n * 32 + lane];
    float4 s1 = xl[N32 + n * 32 + lane];
    float4 o0 = make_float4(fmaxf(fmaf(sn, s0.x, a0.x), 0.f),
                            fmaxf(fmaf(sn, s0.y, a0.y), 0.f),
                            fmaxf(fmaf(sn, s0.z, a0.z), 0.f),
                            fmaxf(fmaf(sn, s0.w, a0.w), 0.f));
    float4 o1 = make_float4(fmaxf(fmaf(sn, s1.x, a1.x), 0.f),
                            fmaxf(fmaf(sn, s1.y, a1.y), 0.f),
                            fmaxf(fmaf(sn, s1.z, a1.z), 0.f),
                            fmaxf(fmaf(sn, s1.w, a1.w), 0.f));
    ((float4*)out)[n * 32 + lane]       = o0;
    ((float4*)out)[N32 + n * 32 + lane] = o1;
}

// ---------------------------------------------------------------- launch
extern "C" void kernel_launch(void* const* d_in, const int* in_sizes, int n_in,
                              void* d_out, int out_size) {
    const float* x    = (const float*)d_in[0];
    const int*   ei   = (const int*)d_in[1];     // int32 (JAX x64 disabled)
    const float* ea   = (const float*)d_in[2];
    const float* W    = (const float*)d_in[3];
    const float* bias = (const float*)d_in[4];
    float*       out  = (float*)d_out;

    const int E  = in_sizes[2];                    // 800000
    const int N  = in_sizes[0] / (NBATCH * FDIM);  // 50000
    const int BN = NBATCH * N;

    k_init<<<(N + 255) / 256, 256>>>(N);
    k_deg_cnt<<<(E + 255) / 256, 256>>>(ei, ea, E);
    k_wt<<<(FDIM * FDIM + 255) / 256, 256>>>(W);
    k_alloc_dinv<<<(N + 255) / 256, 256>>>(N);
    k_fill<<<(E + 255) / 256, 256>>>(ei, ea, E);

    int smem = (FDIM * FDIM + GEMM_ROWS * FDIM) * (int)sizeof(float);  // 96 KB
    cudaFuncSetAttribute(k_gemm, cudaFuncAttributeMaxDynamicSharedMemorySize, smem);
    k_gemm<<<(BN + GEMM_ROWS - 1) / GEMM_ROWS, 256, smem>>>(x, bias, BN);

    k_gather<<<(N * 32 + 255) / 256, 256>>>(out, N);
}

// round 11
// speedup vs baseline: 1.8773x; 1.1852x over previous
#include <cuda_runtime.h>
#include <cuda_bf16.h>
#include <cuda_fp16.h>
#include <cstdint>

// Problem constants (shapes fixed by the dataset)
#define NBATCH 2
#define FDIM   128
#define NMAX   50000
#define EMAX   800000
#define BNPAD  (NBATCH * NMAX + 128)   // pad so GEMM tail stores need no guard

// ----------------------------------------------------------------- scratch
__device__ float g_deg[NMAX];
__device__ float g_dinv[NMAX];
__device__ int   g_cnt[NMAX];
__device__ int   g_rowstart[NMAX];
__device__ int   g_cursor[NMAX];
__device__ int   g_total;
__device__ int2  g_csr[EMAX];                         // {col, bits(norm)}
__device__ __half        g_xh[(size_t)BNPAD * FDIM];  // fp16 x_lin (25.6 MB)
__device__ __nv_bfloat16 g_W1[FDIM * FDIM];           // W hi  (row-major [o][f])
__device__ __nv_bfloat16 g_W2[FDIM * FDIM];           // W residual

// ----------------------------------------------------------------- small kernels
__global__ void k_init(int N) {
    int i = blockIdx.x * blockDim.x + threadIdx.x;
    if (i < N) { g_deg[i] = 1.0f; g_cnt[i] = 0; }
    if (i == 0) g_total = 0;
}
__global__ void k_deg_cnt(const int* __restrict__ ei, const float* __restrict__ ea, int E) {
    int e = blockIdx.x * blockDim.x + threadIdx.x;
    if (e < E) {
        int r = ei[e];
        atomicAdd(&g_deg[r], ea[e]);
        atomicAdd(&g_cnt[r], 1);
    }
}
__global__ void k_wsplit(const float* __restrict__ W) {
    int i = blockIdx.x * blockDim.x + threadIdx.x;
    if (i < FDIM * FDIM) {
        float v = W[i];
        __nv_bfloat16 h = __float2bfloat16(v);
        g_W1[i] = h;
        g_W2[i] = __float2bfloat16(v - __bfloat162float(h));
    }
}
__global__ void k_alloc_dinv(int N) {
    int i = blockIdx.x * blockDim.x + threadIdx.x;
    int lane = threadIdx.x & 31;
    int v = (i < N) ? g_cnt[i] : 0;
    int incl = v;
#pragma unroll
    for (int off = 1; off < 32; off <<= 1) {
        int t = __shfl_up_sync(0xffffffffu, incl, off);
        if (lane >= off) incl += t;
    }
    int excl = incl - v;
    int wsum = __shfl_sync(0xffffffffu, incl, 31);
    int base = 0;
    if (lane == 0 && wsum > 0) base = atomicAdd(&g_total, wsum);
    base = __shfl_sync(0xffffffffu, base, 0);
    if (i < N) {
        int s = base + excl;
        g_rowstart[i] = s;
        g_cursor[i]   = s;
        float d = g_deg[i];
        g_dinv[i] = (d > 0.0f) ? rsqrtf(d) : 0.0f;
    }
}
__global__ void k_fill(const int* __restrict__ ei, const float* __restrict__ ea, int E) {
    int e = blockIdx.x * blockDim.x + threadIdx.x;
    if (e < E) {
        int r = ei[e];
        int c = ei[E + e];
        float norm = g_dinv[r] * ea[e] * g_dinv[c];
        int p = atomicAdd(&g_cursor[r], 1);
        g_csr[p] = make_int2(c, __float_as_int(norm));
    }
}

// ----------------------------------------------------------------- HMMA GEMM
// x_lin = x @ W^T + b via mma.sync.m16n8k16 bf16, 3-term split, fp32 accum,
// fp16 output into g_xh.
//
// SMEM tiles, all [128 rows][128 cols bf16] with row stride 68 words (136 halves):
//   word bank = (68*row + w) mod 32 = (4*row + w) mod 32  -> fragment loads conflict-free.
#define WSTRIDE 68                       // uint32 words per row
#define TILE_W  (128 * WSTRIDE)          // words per tile (8704)

__device__ __forceinline__ void mma_bf16(float c[4], uint32_t a0, uint32_t a1,
                                         uint32_t a2, uint32_t a3,
                                         uint32_t b0, uint32_t b1) {
    asm volatile(
        "mma.sync.aligned.m16n8k16.row.col.f32.bf16.bf16.f32 "
        "{%0,%1,%2,%3}, {%4,%5,%6,%7}, {%8,%9}, {%0,%1,%2,%3};"
        : "+f"(c[0]), "+f"(c[1]), "+f"(c[2]), "+f"(c[3])
        : "r"(a0), "r"(a1), "r"(a2), "r"(a3), "r"(b0), "r"(b1));
}

__global__ void __launch_bounds__(256) k_gemm_mma(const float* __restrict__ x,
                                                  const float* __restrict__ bias, int BN) {
    extern __shared__ uint32_t sm[];
    uint32_t* sA1 = sm;                  // x hi
    uint32_t* sA2 = sm + TILE_W;         // x lo
    uint32_t* sB1 = sm + 2 * TILE_W;     // W hi
    uint32_t* sB2 = sm + 3 * TILE_W;     // W lo
    const int tid  = threadIdx.x;
    const int wid  = tid >> 5;
    const int lane = tid & 31;
    const int row0 = blockIdx.x * 128;

    // Load W hi/lo (row-major [o][f], 64 words/row) into padded smem
    const uint32_t* w1 = (const uint32_t*)g_W1;
    const uint32_t* w2 = (const uint32_t*)g_W2;
    for (int i = tid; i < 128 * 64; i += 256) {
        int r = i >> 6, j = i & 63;
        sB1[r * WSTRIDE + j] = w1[i];
        sB2[r * WSTRIDE + j] = w2[i];
    }
    // Load x rows, split into bf16 hi/lo
    for (int i = tid; i < 128 * 32; i += 256) {
        int r = i >> 5;
        int c4 = (i & 31) << 2;
        float4 v = (row0 + r < BN)
                 ? ((const float4*)x)[(size_t)(row0 + r) * 32 + (c4 >> 2)]
                 : make_float4(0.f, 0.f, 0.f, 0.f);
        __nv_bfloat162 h01 = __floats2bfloat162_rn(v.x, v.y);
        __nv_bfloat162 h23 = __floats2bfloat162_rn(v.z, v.w);
        __nv_bfloat162 l01 = __floats2bfloat162_rn(v.x - __bfloat162float(h01.x),
                                                   v.y - __bfloat162float(h01.y));
        __nv_bfloat162 l23 = __floats2bfloat162_rn(v.z - __bfloat162float(h23.x),
                                                   v.w - __bfloat162float(h23.y));
        int base = r * WSTRIDE + (c4 >> 1);
        sA1[base]     = *(uint32_t*)&h01;
        sA1[base + 1] = *(uint32_t*)&h23;
        sA2[base]     = *(uint32_t*)&l01;
        sA2[base + 1] = *(uint32_t*)&l23;
    }
    __syncthreads();

    const int g = lane >> 2;             // group id (0..7)
    const int t = lane & 3;              // thread in group
    const int m0 = wid * 16;             // this warp's row block

    float acc[16][4];
#pragma unroll
    for (int j = 0; j < 16; j++) {
        acc[j][0] = acc[j][1] = acc[j][2] = acc[j][3] = 0.f;
    }

    const int arow0 = (m0 + g) * WSTRIDE;
    const int arow1 = (m0 + g + 8) * WSTRIDE;

#pragma unroll
    for (int kk = 0; kk < 8; kk++) {
        const int kw = kk * 8 + t;       // word offset of this lane's k pair
        uint32_t ah0 = sA1[arow0 + kw],     ah1 = sA1[arow1 + kw];
        uint32_t ah2 = sA1[arow0 + kw + 4], ah3 = sA1[arow1 + kw + 4];
        uint32_t al0 = sA2[arow0 + kw],     al1 = sA2[arow1 + kw];
        uint32_t al2 = sA2[arow0 + kw + 4], al3 = sA2[arow1 + kw + 4];
#pragma unroll
        for (int j = 0; j < 16; j++) {
            const int brow = (j * 8 + g) * WSTRIDE;
            uint32_t bh0 = sB1[brow + kw], bh1 = sB1[brow + kw + 4];
            uint32_t bl0 = sB2[brow + kw], bl1 = sB2[brow + kw + 4];
            mma_bf16(acc[j], ah0, ah1, ah2, ah3, bh0, bh1);   // x1*W1
            mma_bf16(acc[j], al0, al1, al2, al3, bh0, bh1);   // x2*W1
            mma_bf16(acc[j], ah0, ah1, ah2, ah3, bl0, bl1);   // x1*W2
        }
    }

    // Epilogue: + bias, fp16 pack, store. g_xh is padded -> no row guard needed.
    uint32_t* xo = (uint32_t*)g_xh;      // 64 words per row
    const int r0 = row0 + m0 + g;
    const int r1 = r0 + 8;
#pragma unroll
    for (int j = 0; j < 16; j++) {
        float bx = bias[j * 8 + 2 * t];
        float by = bias[j * 8 + 2 * t + 1];
        __half2 h0 = __floats2half2_rn(acc[j][0] + bx, acc[j][1] + by);
        __half2 h1 = __floats2half2_rn(acc[j][2] + bx, acc[j][3] + by);
        xo[(size_t)r0 * 64 + j * 4 + t] = *(uint32_t*)&h0;
        xo[(size_t)r1 * 64 + j * 4 + t] = *(uint32_t*)&h1;
    }
}

// ----------------------------------------------------------------- gather (warp/node), fp16 src
__global__ void k_gather(float* __restrict__ out, int N) {
    int n = (blockIdx.x * blockDim.x + threadIdx.x) >> 5;
    int lane = threadIdx.x & 31;
    if (n >= N) return;

    const int start = g_rowstart[n];
    const int num   = g_cnt[n];
    const uint2* __restrict__ xh = (const uint2*)g_xh;   // 32 uint2 (4 halfs) per row

    float4 a0 = make_float4(0.f, 0.f, 0.f, 0.f);
    float4 a1 = make_float4(0.f, 0.f, 0.f, 0.f);

    for (int i = 0; i < num; i++) {
        int2 ed = g_csr[start + i];
        int   c = ed.x;
        float w = __int_as_float(ed.y);
        uint2 u0 = xh[(size_t)c * 32 + lane];
        uint2 u1 = xh[((size_t)N + c) * 32 + lane];
        float2 p0 = __half22float2(*(__half2*)&u0.x);
        float2 p1 = __half22float2(*(__half2*)&u0.y);
        float2 q0 = __half22float2(*(__half2*)&u1.x);
        float2 q1 = __half22float2(*(__half2*)&u1.y);
        a0.x = fmaf(w, p0.x, a0.x); a0.y = fmaf(w, p0.y, a0.y);
        a0.z = fmaf(w, p1.x, a0.z); a0.w = fmaf(w, p1.y, a0.w);
        a1.x = fmaf(w, q0.x, a1.x); a1.y = fmaf(w, q0.y, a1.y);
        a1.z = fmaf(w, q1.x, a1.z); a1.w = fmaf(w, q1.y, a1.w);
    }

    float di = g_dinv[n];
    float sn = di * di;
    uint2 s0 = xh[(size_t)n * 32 + lane];
    uint2 s1 = xh[((size_t)N + n) * 32 + lane];
    float2 sp0 = __half22float2(*(__half2*)&s0.x);
    float2 sp1 = __half22float2(*(__half2*)&s0.y);
    float2 sq0 = __half22float2(*(__half2*)&s1.x);
    float2 sq1 = __half22float2(*(__half2*)&s1.y);

    float4 o0 = make_float4(fmaxf(fmaf(sn, sp0.x, a0.x), 0.f),
                            fmaxf(fmaf(sn, sp0.y, a0.y), 0.f),
                            fmaxf(fmaf(sn, sp1.x, a0.z), 0.f),
                            fmaxf(fmaf(sn, sp1.y, a0.w), 0.f));
    float4 o1 = make_float4(fmaxf(fmaf(sn, sq0.x, a1.x), 0.f),
                            fmaxf(fmaf(sn, sq0.y, a1.y), 0.f),
                            fmaxf(fmaf(sn, sq1.x, a1.z), 0.f),
                            fmaxf(fmaf(sn, sq1.y, a1.w), 0.f));
    ((float4*)out)[(size_t)n * 32 + lane]       = o0;
    ((float4*)out)[((size_t)N + n) * 32 + lane] = o1;
}

// ----------------------------------------------------------------- launch
extern "C" void kernel_launch(void* const* d_in, const int* in_sizes, int n_in,
                              void* d_out, int out_size) {
    const float* x    = (const float*)d_in[0];
    const int*   ei   = (const int*)d_in[1];     // int32 (JAX x64 disabled)
    const float* ea   = (const float*)d_in[2];
    const float* W    = (const float*)d_in[3];
    const float* bias = (const float*)d_in[4];
    float*       out  = (float*)d_out;

    const int E  = in_sizes[2];                    // 800000
    const int N  = in_sizes[0] / (NBATCH * FDIM);  // 50000
    const int BN = NBATCH * N;

    k_init<<<(N + 255) / 256, 256>>>(N);
    k_deg_cnt<<<(E + 255) / 256, 256>>>(ei, ea, E);
    k_wsplit<<<(FDIM * FDIM + 255) / 256, 256>>>(W);
    k_alloc_dinv<<<(N + 255) / 256, 256>>>(N);
    k_fill<<<(E + 255) / 256, 256>>>(ei, ea, E);

    int smem = 4 * TILE_W * (int)sizeof(uint32_t);   // 139,264 B
    cudaFuncSetAttribute(k_gemm_mma, cudaFuncAttributeMaxDynamicSharedMemorySize, smem);
    k_gemm_mma<<<(BN + 127) / 128, 256, smem>>>(x, bias, BN);

    k_gather<<<(N * 32 + 255) / 256, 256>>>(out, N);
}

// round 13
// speedup vs baseline: 2.0678x; 1.1015x over previous
#include <cuda_runtime.h>
#include <cuda_bf16.h>
#include <cuda_fp16.h>
#include <cstdint>

// Problem constants (shapes fixed by the dataset)
#define NBATCH 2
#define FDIM   128
#define NMAX   50000
#define EMAX   800000
#define BNPAD  (NBATCH * NMAX + 128)   // pad so GEMM tail stores need no guard

// ----------------------------------------------------------------- scratch
__device__ float g_deg[NMAX];
__device__ float g_dinv[NMAX];
__device__ int   g_cnt[NMAX];
__device__ int   g_rowstart[NMAX];
__device__ int   g_cursor[NMAX];
__device__ int   g_total;
__device__ int2  g_csr[EMAX];                         // {col, bits(norm)}
__device__ __half        g_xh[(size_t)BNPAD * FDIM];  // fp16 x_lin (25.6 MB)
__device__ __nv_bfloat16 g_W1[FDIM * FDIM];           // W hi  (row-major [o][f])
__device__ __nv_bfloat16 g_W2[FDIM * FDIM];           // W residual

// ----------------------------------------------------------------- helpers
__device__ __forceinline__ uint32_t smem_u32(const void* p) {
    uint32_t a;
    asm("{ .reg .u64 t; cvta.to.shared.u64 t, %1; cvt.u32.u64 %0, t; }" : "=r"(a) : "l"(p));
    return a;
}
__device__ __forceinline__ void ldsm4(uint32_t& r0, uint32_t& r1, uint32_t& r2,
                                      uint32_t& r3, uint32_t addr) {
    asm volatile("ldmatrix.sync.aligned.m8n8.x4.shared.b16 {%0,%1,%2,%3}, [%4];"
                 : "=r"(r0), "=r"(r1), "=r"(r2), "=r"(r3) : "r"(addr));
}
__device__ __forceinline__ void mma_bf16(float c[4], uint32_t a0, uint32_t a1,
                                         uint32_t a2, uint32_t a3,
                                         uint32_t b0, uint32_t b1) {
    asm volatile(
        "mma.sync.aligned.m16n8k16.row.col.f32.bf16.bf16.f32 "
        "{%0,%1,%2,%3}, {%4,%5,%6,%7}, {%8,%9}, {%0,%1,%2,%3};"
        : "+f"(c[0]), "+f"(c[1]), "+f"(c[2]), "+f"(c[3])
        : "r"(a0), "r"(a1), "r"(a2), "r"(a3), "r"(b0), "r"(b1));
}

// ----------------------------------------------------------------- K1: init + W split (fused)
__global__ void k_initw(const float* __restrict__ W, int N) {
    int i = blockIdx.x * blockDim.x + threadIdx.x;
    if (i < N) { g_deg[i] = 1.0f; g_cnt[i] = 0; }
    if (i == 0) g_total = 0;
    if (i < FDIM * FDIM) {
        float v = W[i];
        __nv_bfloat16 h = __float2bfloat16(v);
        g_W1[i] = h;
        g_W2[i] = __float2bfloat16(v - __bfloat162float(h));
    }
}

// ----------------------------------------------------------------- K3: segment alloc + dinv
__global__ void k_alloc_dinv(int N) {
    int i = blockIdx.x * blockDim.x + threadIdx.x;
    int lane = threadIdx.x & 31;
    int v = (i < N) ? g_cnt[i] : 0;
    int incl = v;
#pragma unroll
    for (int off = 1; off < 32; off <<= 1) {
        int t = __shfl_up_sync(0xffffffffu, incl, off);
        if (lane >= off) incl += t;
    }
    int excl = incl - v;
    int wsum = __shfl_sync(0xffffffffu, incl, 31);
    int base = 0;
    if (lane == 0 && wsum > 0) base = atomicAdd(&g_total, wsum);
    base = __shfl_sync(0xffffffffu, base, 0);
    if (i < N) {
        int s = base + excl;
        g_rowstart[i] = s;
        g_cursor[i]   = s;
        float d = g_deg[i];
        g_dinv[i] = (d > 0.0f) ? rsqrtf(d) : 0.0f;
    }
}

// ----------------------------------------------------------------- K4: fill CSR (premultiplied norm)
__global__ void k_fill(const int* __restrict__ ei, const float* __restrict__ ea, int E) {
    int e = blockIdx.x * blockDim.x + threadIdx.x;
    if (e < E) {
        int r = ei[e];
        int c = ei[E + e];
        float norm = g_dinv[r] * ea[e] * g_dinv[c];
        int p = atomicAdd(&g_cursor[r], 1);
        g_csr[p] = make_int2(c, __float_as_int(norm));
    }
}

// ----------------------------------------------------------------- K2: HMMA GEMM + embedded deg/cnt
// x_lin = x @ W^T + b via mma.sync m16n8k16 bf16, 3-term split, fp32 accum, fp16 out.
// Each CTA also accumulates deg/cnt for its slice of edges (hidden under MMA work).
#define WSTRIDE 68                       // uint32 words per smem row (272 B)
#define TILE_W  (128 * WSTRIDE)
#define TILE_B  (TILE_W * 4)             // bytes per tile

__global__ void __launch_bounds__(256) k_gemm_mma(const float* __restrict__ x,
                                                  const float* __restrict__ bias,
                                                  const int* __restrict__ ei,
                                                  const float* __restrict__ ea,
                                                  int BN, int E, int epb) {
    extern __shared__ uint32_t sm[];
    uint32_t* sA1 = sm;                  // x hi
    uint32_t* sA2 = sm + TILE_W;         // x lo
    uint32_t* sB1 = sm + 2 * TILE_W;     // W hi
    uint32_t* sB2 = sm + 3 * TILE_W;     // W lo
    const int tid  = threadIdx.x;
    const int wid  = tid >> 5;
    const int lane = tid & 31;
    const int row0 = blockIdx.x * 128;

    // ---- embedded deg/cnt slice (fire-and-forget REDs, hidden under GEMM) ----
    {
        int e0 = blockIdx.x * epb;
        int e1 = min(e0 + epb, E);
        for (int e = e0 + tid; e < e1; e += 256) {
            int r = ei[e];
            atomicAdd(&g_deg[r], ea[e]);
            atomicAdd(&g_cnt[r], 1);
        }
    }

    // ---- stage tiles ----
    const uint32_t* w1 = (const uint32_t*)g_W1;
    const uint32_t* w2 = (const uint32_t*)g_W2;
    for (int i = tid; i < 128 * 64; i += 256) {
        int r = i >> 6, j = i & 63;
        sB1[r * WSTRIDE + j] = w1[i];
        sB2[r * WSTRIDE + j] = w2[i];
    }
    for (int i = tid; i < 128 * 32; i += 256) {
        int r = i >> 5;
        int c4 = (i & 31) << 2;
        float4 v = (row0 + r < BN)
                 ? ((const float4*)x)[(size_t)(row0 + r) * 32 + (c4 >> 2)]
                 : make_float4(0.f, 0.f, 0.f, 0.f);
        __nv_bfloat162 h01 = __floats2bfloat162_rn(v.x, v.y);
        __nv_bfloat162 h23 = __floats2bfloat162_rn(v.z, v.w);
        __nv_bfloat162 l01 = __floats2bfloat162_rn(v.x - __bfloat162float(h01.x),
                                                   v.y - __bfloat162float(h01.y));
        __nv_bfloat162 l23 = __floats2bfloat162_rn(v.z - __bfloat162float(h23.x),
                                                   v.w - __bfloat162float(h23.y));
        int base = r * WSTRIDE + (c4 >> 1);
        sA1[base]     = *(uint32_t*)&h01;
        sA1[base + 1] = *(uint32_t*)&h23;
        sA2[base]     = *(uint32_t*)&l01;
        sA2[base + 1] = *(uint32_t*)&l23;
    }
    __syncthreads();

    const int g = lane >> 2;
    const int t = lane & 3;
    const int m0 = wid * 16;

    float acc[16][4];
#pragma unroll
    for (int j = 0; j < 16; j++)
        acc[j][0] = acc[j][1] = acc[j][2] = acc[j][3] = 0.f;

    // ldmatrix per-lane address patterns (byte offsets within a tile)
    const uint32_t sb = smem_u32(sm);
    // A: lanes 0-15 -> rows m0+(lane&15), k+0; lanes 16-31 -> same rows, k+16B
    const uint32_t aoff = (uint32_t)(m0 + (lane & 15)) * 272 + (uint32_t)((lane >> 4) << 4);
    // B: lanes 0-7 rows 0-7 k+0 | 8-15 rows 0-7 k+16 | 16-23 rows 8-15 k+0 | 24-31 rows 8-15 k+16
    const uint32_t boff = (uint32_t)(((lane >> 4) << 3) | (lane & 7)) * 272
                        + (uint32_t)((lane & 8) ? 16 : 0);

#pragma unroll
    for (int kk = 0; kk < 8; kk++) {
        const uint32_t ka = (uint32_t)kk * 32;
        uint32_t ah0, ah1, ah2, ah3, al0, al1, al2, al3;
        ldsm4(ah0, ah1, ah2, ah3, sb + aoff + ka);              // A1 (x hi)
        ldsm4(al0, al1, al2, al3, sb + TILE_B + aoff + ka);     // A2 (x lo)
#pragma unroll
        for (int j2 = 0; j2 < 8; j2++) {
            const uint32_t bb = boff + (uint32_t)j2 * (16 * 272) + ka;
            uint32_t bh00, bh01, bh10, bh11, bl00, bl01, bl10, bl11;
            ldsm4(bh00, bh01, bh10, bh11, sb + 2 * TILE_B + bb);  // W hi: b0/b1 of j=2*j2, 2*j2+1
            ldsm4(bl00, bl01, bl10, bl11, sb + 3 * TILE_B + bb);  // W lo
            mma_bf16(acc[2 * j2],     ah0, ah1, ah2, ah3, bh00, bh01);  // x1*W1
            mma_bf16(acc[2 * j2],     al0, al1, al2, al3, bh00, bh01);  // x2*W1
            mma_bf16(acc[2 * j2],     ah0, ah1, ah2, ah3, bl00, bl01);  // x1*W2
            mma_bf16(acc[2 * j2 + 1], ah0, ah1, ah2, ah3, bh10, bh11);
            mma_bf16(acc[2 * j2 + 1], al0, al1, al2, al3, bh10, bh11);
            mma_bf16(acc[2 * j2 + 1], ah0, ah1, ah2, ah3, bl10, bl11);
        }
    }

    // Epilogue: + bias, fp16 pack, store (g_xh padded -> no guard)
    uint32_t* xo = (uint32_t*)g_xh;      // 64 words per row
    const int r0 = row0 + m0 + g;
    const int r1 = r0 + 8;
#pragma unroll
    for (int j = 0; j < 16; j++) {
        float bx = bias[j * 8 + 2 * t];
        float by = bias[j * 8 + 2 * t + 1];
        __half2 h0 = __floats2half2_rn(acc[j][0] + bx, acc[j][1] + by);
        __half2 h1 = __floats2half2_rn(acc[j][2] + bx, acc[j][3] + by);
        xo[(size_t)r0 * 64 + j * 4 + t] = *(uint32_t*)&h0;
        xo[(size_t)r1 * 64 + j * 4 + t] = *(uint32_t*)&h1;
    }
}

// ----------------------------------------------------------------- K5: gather (warp/node), fp16 src
__global__ void k_gather(float* __restrict__ out, int N) {
    int n = (blockIdx.x * blockDim.x + threadIdx.x) >> 5;
    int lane = threadIdx.x & 31;
    if (n >= N) return;

    const int start = g_rowstart[n];
    const int num   = g_cnt[n];
    const uint2* __restrict__ xh = (const uint2*)g_xh;

    float4 a0 = make_float4(0.f, 0.f, 0.f, 0.f);
    float4 a1 = make_float4(0.f, 0.f, 0.f, 0.f);

    for (int i = 0; i < num; i++) {
        int2 ed = g_csr[start + i];
        int   c = ed.x;
        float w = __int_as_float(ed.y);
        uint2 u0 = xh[(size_t)c * 32 + lane];
        uint2 u1 = xh[((size_t)N + c) * 32 + lane];
        float2 p0 = __half22float2(*(__half2*)&u0.x);
        float2 p1 = __half22float2(*(__half2*)&u0.y);
        float2 q0 = __half22float2(*(__half2*)&u1.x);
        float2 q1 = __half22float2(*(__half2*)&u1.y);
        a0.x = fmaf(w, p0.x, a0.x); a0.y = fmaf(w, p0.y, a0.y);
        a0.z = fmaf(w, p1.x, a0.z); a0.w = fmaf(w, p1.y, a0.w);
        a1.x = fmaf(w, q0.x, a1.x); a1.y = fmaf(w, q0.y, a1.y);
        a1.z = fmaf(w, q1.x, a1.z); a1.w = fmaf(w, q1.y, a1.w);
    }

    float di = g_dinv[n];
    float sn = di * di;
    uint2 s0 = xh[(size_t)n * 32 + lane];
    uint2 s1 = xh[((size_t)N + n) * 32 + lane];
    float2 sp0 = __half22float2(*(__half2*)&s0.x);
    float2 sp1 = __half22float2(*(__half2*)&s0.y);
    float2 sq0 = __half22float2(*(__half2*)&s1.x);
    float2 sq1 = __half22float2(*(__half2*)&s1.y);

    float4 o0 = make_float4(fmaxf(fmaf(sn, sp0.x, a0.x), 0.f),
                            fmaxf(fmaf(sn, sp0.y, a0.y), 0.f),
                            fmaxf(fmaf(sn, sp1.x, a0.z), 0.f),
                            fmaxf(fmaf(sn, sp1.y, a0.w), 0.f));
    float4 o1 = make_float4(fmaxf(fmaf(sn, sq0.x, a1.x), 0.f),
                            fmaxf(fmaf(sn, sq0.y, a1.y), 0.f),
                            fmaxf(fmaf(sn, sq1.x, a1.z), 0.f),
                            fmaxf(fmaf(sn, sq1.y, a1.w), 0.f));
    ((float4*)out)[(size_t)n * 32 + lane]       = o0;
    ((float4*)out)[((size_t)N + n) * 32 + lane] = o1;
}

// ----------------------------------------------------------------- launch
extern "C" void kernel_launch(void* const* d_in, const int* in_sizes, int n_in,
                              void* d_out, int out_size) {
    const float* x    = (const float*)d_in[0];
    const int*   ei   = (const int*)d_in[1];     // int32 (JAX x64 disabled)
    const float* ea   = (const float*)d_in[2];
    const float* W    = (const float*)d_in[3];
    const float* bias = (const float*)d_in[4];
    float*       out  = (float*)d_out;

    const int E  = in_sizes[2];                    // 800000
    const int N  = in_sizes[0] / (NBATCH * FDIM);  // 50000
    const int BN = NBATCH * N;

    k_initw<<<(N + 255) / 256, 256>>>(W, N);

    int grid = (BN + 127) / 128;
    int epb  = (E + grid - 1) / grid;
    int smem = 4 * TILE_W * (int)sizeof(uint32_t);   // 139,264 B
    cudaFuncSetAttribute(k_gemm_mma, cudaFuncAttributeMaxDynamicSharedMemorySize, smem);
    k_gemm_mma<<<grid, 256, smem>>>(x, bias, ei, ea, BN, E, epb);

    k_alloc_dinv<<<(N + 255) / 256, 256>>>(N);
    k_fill<<<(E + 255) / 256, 256>>>(ei, ea, E);
    k_gather<<<(N * 32 + 255) / 256, 256>>>(out, N);
}